// round 11
// baseline (speedup 1.0000x reference)
#include <cuda_runtime.h>
#include <cuda_bf16.h>
#include <cstdint>

#define DD 128

// 51.2 MB scratch for support1 = X @ W1 (static device array: allowed, no alloc)
__device__ float g_s1[100000 * DD];

// ---------------------------------------------------------------------------
// TF32 helpers
// ---------------------------------------------------------------------------
__device__ __forceinline__ uint32_t cvt_tf32(float x) {
    uint32_t u;
    asm("cvt.rna.tf32.f32 %0, %1;" : "=r"(u) : "f"(x));
    return u;
}
__device__ __forceinline__ void split_tf32(float x, float& hi, float& lo) {
    uint32_t uh = cvt_tf32(x);
    hi = __uint_as_float(uh);
    lo = __uint_as_float(cvt_tf32(x - hi));
}

#define MMA_TF32(d, a, b)                                                     \
    asm volatile(                                                             \
        "mma.sync.aligned.m16n8k8.row.col.f32.tf32.tf32.f32 "                 \
        "{%0,%1,%2,%3},{%4,%5,%6,%7},{%8,%9},{%0,%1,%2,%3};"                  \
        : "+f"((d)[0]), "+f"((d)[1]), "+f"((d)[2]), "+f"((d)[3])              \
        : "r"((a)[0]), "r"((a)[1]), "r"((a)[2]), "r"((a)[3]),                 \
          "r"((b)[0]), "r"((b)[1]))

// smem layout: float2 (hi,lo) packed. Double buffered.
#define XS2_STRIDE 36                 // 32 cols + 4 pad (float2 units)
#define WS2_STRIDE 132                // 128 cols + 4 pad
#define XS2_ELEMS (128 * XS2_STRIDE)  // 4608 float2
#define WS2_ELEMS (32 * WS2_STRIDE)   // 4224 float2
#define BUF_ELEMS (XS2_ELEMS + WS2_ELEMS)      // 8832 float2
#define SMEM_BYTES (2 * BUF_ELEMS * 8)         // 141312 B

// ---------------------------------------------------------------------------
// 3xTF32 GEMM, double-buffered, hi/lo packed (LDS.64 fragment loads).
// One 128x128 output tile per block; blockIdx.y: 0 -> out=X@W0+bias, 1 -> g_s1=X@W1.
// 8 warps: warpM = wid&3 (32 rows), warpN = wid>>2 (64 cols).
// ---------------------------------------------------------------------------
__global__ __launch_bounds__(256) void gemm_tf32_kernel(
    const float* __restrict__ X, const float* __restrict__ W0,
    const float* __restrict__ W1, const float* __restrict__ bias,
    float* __restrict__ out, int N)
{
    extern __shared__ float2 sm2[];

    const float* W = (blockIdx.y == 0) ? W0 : W1;

    const int tid   = threadIdx.x;
    const int lane  = tid & 31;
    const int gid   = lane >> 2;       // 0..7
    const int tig   = lane & 3;        // 0..3
    const int wid   = tid >> 5;
    const int rbase = (wid & 3) * 32;
    const int nbase = (wid >> 2) * 64;
    const int row0  = blockIdx.x * 128;

    // per-thread load coordinates (fixed across chunks)
    int xr_r[4], xr_q[4], wr_r[4], wr_q[4];
#pragma unroll
    for (int i = 0; i < 4; i++) {
        int idx = tid + i * 256;
        xr_r[i] = idx >> 3;   xr_q[i] = idx & 7;    // X: 128 rows x 8 quads
        wr_r[i] = idx >> 5;   wr_q[i] = idx & 31;   // W: 32 rows x 32 quads
    }

    float4 xv[4], wv[4];

    auto load_chunk = [&](int kc) {
#pragma unroll
        for (int i = 0; i < 4; i++) {
            int gr = row0 + xr_r[i];
            if (gr >= N) gr = N - 1;
            xv[i] = *(const float4*)&X[(size_t)gr * DD + kc + xr_q[i] * 4];
            wv[i] = *(const float4*)&W[(size_t)(kc + wr_r[i]) * DD + wr_q[i] * 4];
        }
    };
    auto store_chunk = [&](int buf) {
        float2* Xb = sm2 + (size_t)buf * BUF_ELEMS;
        float2* Wb = Xb + XS2_ELEMS;
#pragma unroll
        for (int i = 0; i < 4; i++) {
            float h0, l0, h1, l1, h2, l2, h3, l3;
            split_tf32(xv[i].x, h0, l0); split_tf32(xv[i].y, h1, l1);
            split_tf32(xv[i].z, h2, l2); split_tf32(xv[i].w, h3, l3);
            float2* p = Xb + xr_r[i] * XS2_STRIDE + xr_q[i] * 4;
            *(float4*)&p[0] = make_float4(h0, l0, h1, l1);
            *(float4*)&p[2] = make_float4(h2, l2, h3, l3);
            split_tf32(wv[i].x, h0, l0); split_tf32(wv[i].y, h1, l1);
            split_tf32(wv[i].z, h2, l2); split_tf32(wv[i].w, h3, l3);
            float2* q = Wb + wr_r[i] * WS2_STRIDE + wr_q[i] * 4;
            *(float4*)&q[0] = make_float4(h0, l0, h1, l1);
            *(float4*)&q[2] = make_float4(h2, l2, h3, l3);
        }
    };

    float cd[2][8][4];
#pragma unroll
    for (int mt = 0; mt < 2; mt++)
#pragma unroll
        for (int nt = 0; nt < 8; nt++)
#pragma unroll
            for (int j = 0; j < 4; j++) cd[mt][nt][j] = 0.f;

    // prologue
    load_chunk(0);
    store_chunk(0);
    __syncthreads();

#pragma unroll
    for (int kc = 0; kc < 4; kc++) {
        const int cur = kc & 1;
        if (kc < 3) load_chunk((kc + 1) * 32);   // global loads in flight

        const float2* Xb = sm2 + (size_t)cur * BUF_ELEMS;
        const float2* Wb = Xb + XS2_ELEMS;

#pragma unroll
        for (int k8 = 0; k8 < 4; k8++) {
            const int kk = k8 * 8;
            float2 a2[2][4];
#pragma unroll
            for (int mt = 0; mt < 2; mt++) {
                int r = rbase + mt * 16 + gid;
                a2[mt][0] = Xb[r * XS2_STRIDE + kk + tig];
                a2[mt][1] = Xb[(r + 8) * XS2_STRIDE + kk + tig];
                a2[mt][2] = Xb[r * XS2_STRIDE + kk + tig + 4];
                a2[mt][3] = Xb[(r + 8) * XS2_STRIDE + kk + tig + 4];
            }
            uint32_t ah[2][4], al[2][4];
#pragma unroll
            for (int mt = 0; mt < 2; mt++)
#pragma unroll
                for (int j = 0; j < 4; j++) {
                    ah[mt][j] = __float_as_uint(a2[mt][j].x);
                    al[mt][j] = __float_as_uint(a2[mt][j].y);
                }
#pragma unroll
            for (int nt = 0; nt < 8; nt++) {
                int ncol = nbase + nt * 8 + gid;
                float2 b0 = Wb[(kk + tig) * WS2_STRIDE + ncol];
                float2 b1 = Wb[(kk + tig + 4) * WS2_STRIDE + ncol];
                uint32_t bh[2] = {__float_as_uint(b0.x), __float_as_uint(b1.x)};
                uint32_t bl[2] = {__float_as_uint(b0.y), __float_as_uint(b1.y)};
#pragma unroll
                for (int mt = 0; mt < 2; mt++) {
                    MMA_TF32(cd[mt][nt], ah[mt], bh);   // hi*hi
                    MMA_TF32(cd[mt][nt], ah[mt], bl);   // hi*lo
                    MMA_TF32(cd[mt][nt], al[mt], bh);   // lo*hi
                }
            }
        }

        if (kc < 3) store_chunk(cur ^ 1);
        __syncthreads();
    }

    float* dst = (blockIdx.y == 0) ? out : g_s1;
    const bool addb = (blockIdx.y == 0);

#pragma unroll
    for (int nt = 0; nt < 8; nt++) {
        int col = nbase + nt * 8 + tig * 2;
        float b0 = addb ? bias[col] : 0.f;
        float b1 = addb ? bias[col + 1] : 0.f;
#pragma unroll
        for (int mt = 0; mt < 2; mt++) {
            int r0 = row0 + rbase + mt * 16 + gid;
            int r1 = r0 + 8;
            if (r0 < N) {
                float2 t = make_float2(cd[mt][nt][0] + b0, cd[mt][nt][1] + b1);
                *(float2*)&dst[(size_t)r0 * DD + col] = t;
            }
            if (r1 < N) {
                float2 t = make_float2(cd[mt][nt][2] + b0, cd[mt][nt][3] + b1);
                *(float2*)&dst[(size_t)r1 * DD + col] = t;
            }
        }
    }
}

// ---------------------------------------------------------------------------
// Edge aggregation (R8-proven, ~154 us, at L2 roofline): one warp per 32-edge
// batch, coalesced index loads, 4-deep gather->red pipeline, red.add.v4.f32.
// ---------------------------------------------------------------------------
__global__ __launch_bounds__(256) void edge_kernel(
    const int* __restrict__ ei, const float* __restrict__ ev,
    float* __restrict__ out, int E)
{
    const int lane = threadIdx.x & 31;
    int wglob = blockIdx.x * 8 + (threadIdx.x >> 5);
    int e0 = wglob * 32;
    if (e0 >= E) return;

    int e = e0 + lane;
    bool valid = e < E;
    int src = valid ? __ldg(&ei[e]) : 0;
    int dst = valid ? __ldg(&ei[E + e]) : 0;
    float a = valid ? __ldg(&ev[e]) : 0.f;   // a=0 => red adds 0: harmless

    const unsigned FULL = 0xffffffffu;
#pragma unroll 1
    for (int j0 = 0; j0 < 32; j0 += 4) {
        float4 v[4];
        int d[4];
        float s[4];
#pragma unroll
        for (int jj = 0; jj < 4; jj++) {
            int j = j0 + jj;
            int sj = __shfl_sync(FULL, src, j);
            d[jj] = __shfl_sync(FULL, dst, j);
            s[jj] = __shfl_sync(FULL, a, j);
            v[jj] = *(const float4*)(g_s1 + (size_t)sj * DD + lane * 4);
        }
#pragma unroll
        for (int jj = 0; jj < 4; jj++) {
            float4 t = v[jj];
            float sc = s[jj];
            t.x *= sc; t.y *= sc; t.z *= sc; t.w *= sc;
            float* p = out + (size_t)d[jj] * DD + lane * 4;
            asm volatile("red.global.add.v4.f32 [%0], {%1,%2,%3,%4};"
                         :: "l"(p), "f"(t.x), "f"(t.y), "f"(t.z), "f"(t.w)
                         : "memory");
        }
    }
}

extern "C" void kernel_launch(void* const* d_in, const int* in_sizes, int n_in,
                              void* d_out, int out_size)
{
    const float* X    = (const float*)d_in[0];   // [N,128] f32
    const int*   ei   = (const int*)d_in[1];     // [2,E] int32
    const float* ev   = (const float*)d_in[2];   // [E] f32
    const float* W0   = (const float*)d_in[3];   // [128,128] f32
    const float* W1   = (const float*)d_in[4];   // [128,128] f32
    const float* bias = (const float*)d_in[5];   // [128] f32
    float* out = (float*)d_out;

    int N = in_sizes[0] / DD;
    int E = in_sizes[2];

    cudaFuncSetAttribute(gemm_tf32_kernel,
                         cudaFuncAttributeMaxDynamicSharedMemorySize, SMEM_BYTES);

    // k1: 3xTF32 tensor-core dual GEMM, double-buffered, hi/lo packed
    int GX = (N + 127) / 128;
    gemm_tf32_kernel<<<dim3(GX, 2), 256, SMEM_BYTES>>>(X, W0, W1, bias, out, N);

    // k2: out[dst] += ev * g_s1[src], warp-batched
    int EB = (E + 32 * 8 - 1) / (32 * 8);        // 6250 blocks
    edge_kernel<<<EB, 256>>>(ei, ev, out, E);
}

// round 12
// speedup vs baseline: 1.0871x; 1.0871x over previous
#include <cuda_runtime.h>
#include <cuda_bf16.h>
#include <cstdint>

#define DD 128

// 51.2 MB scratch for support1 = X @ W1 (static device array: allowed, no alloc)
__device__ float g_s1[100000 * DD];

// ---------------------------------------------------------------------------
// TF32 helpers
// ---------------------------------------------------------------------------
__device__ __forceinline__ uint32_t cvt_tf32(float x) {
    uint32_t u;
    asm("cvt.rna.tf32.f32 %0, %1;" : "=r"(u) : "f"(x));
    return u;
}
__device__ __forceinline__ void split_tf32(float x, float& hi, float& lo) {
    uint32_t uh = cvt_tf32(x);
    hi = __uint_as_float(uh);
    lo = __uint_as_float(cvt_tf32(x - hi));
}

#define MMA_TF32(d, a, b)                                                     \
    asm volatile(                                                             \
        "mma.sync.aligned.m16n8k8.row.col.f32.tf32.tf32.f32 "                 \
        "{%0,%1,%2,%3},{%4,%5,%6,%7},{%8,%9},{%0,%1,%2,%3};"                  \
        : "+f"((d)[0]), "+f"((d)[1]), "+f"((d)[2]), "+f"((d)[3])              \
        : "r"((a)[0]), "r"((a)[1]), "r"((a)[2]), "r"((a)[3]),                 \
          "r"((b)[0]), "r"((b)[1]))

// smem: hi/lo packed as float2, single buffer (R10 structure + packing only)
#define XS2_STRIDE 36                 // 32 cols + 4 pad (float2 units)
#define WS2_STRIDE 132                // 128 cols + 4 pad
#define XS2_ELEMS (128 * XS2_STRIDE)  // 4608 float2
#define WS2_ELEMS (32 * WS2_STRIDE)   // 4224 float2
#define SMEM_BYTES ((XS2_ELEMS + WS2_ELEMS) * 8)   // 70656 B

// ---------------------------------------------------------------------------
// 3xTF32 GEMM, single-buffered, hi/lo packed (LDS.64 fragment loads).
// One 128x128 tile per block; blockIdx.y: 0 -> out=X@W0+bias, 1 -> g_s1=X@W1.
// 8 warps: warpM = wid&3 (32 rows), warpN = wid>>2 (64 cols).
// ---------------------------------------------------------------------------
__global__ __launch_bounds__(256) void gemm_tf32_kernel(
    const float* __restrict__ X, const float* __restrict__ W0,
    const float* __restrict__ W1, const float* __restrict__ bias,
    float* __restrict__ out, int N)
{
    extern __shared__ float2 sm2[];
    float2* Xb = sm2;
    float2* Wb = Xb + XS2_ELEMS;

    const float* W = (blockIdx.y == 0) ? W0 : W1;

    const int tid   = threadIdx.x;
    const int lane  = tid & 31;
    const int gid   = lane >> 2;       // 0..7
    const int tig   = lane & 3;        // 0..3
    const int wid   = tid >> 5;
    const int rbase = (wid & 3) * 32;
    const int nbase = (wid >> 2) * 64;
    const int row0  = blockIdx.x * 128;

    float cd[2][8][4];
#pragma unroll
    for (int mt = 0; mt < 2; mt++)
#pragma unroll
        for (int nt = 0; nt < 8; nt++)
#pragma unroll
            for (int j = 0; j < 4; j++) cd[mt][nt][j] = 0.f;

    for (int kc = 0; kc < DD; kc += 32) {
        __syncthreads();
        // X chunk: 128x32 = 1024 float4 loads, 4/thread; split+pack on fill
#pragma unroll
        for (int i = 0; i < 4; i++) {
            int idx = tid + i * 256;
            int r = idx >> 3;          // 0..127
            int q = idx & 7;           // 0..7
            int gr = row0 + r;
            if (gr >= N) gr = N - 1;
            float4 v = *(const float4*)&X[(size_t)gr * DD + kc + q * 4];
            float h0, l0, h1, l1, h2, l2, h3, l3;
            split_tf32(v.x, h0, l0); split_tf32(v.y, h1, l1);
            split_tf32(v.z, h2, l2); split_tf32(v.w, h3, l3);
            float2* p = Xb + r * XS2_STRIDE + q * 4;
            *(float4*)&p[0] = make_float4(h0, l0, h1, l1);
            *(float4*)&p[2] = make_float4(h2, l2, h3, l3);
        }
        // W chunk: 32x128 = 1024 float4 loads, 4/thread
#pragma unroll
        for (int i = 0; i < 4; i++) {
            int idx = tid + i * 256;
            int r = idx >> 5;          // 0..31
            int q = idx & 31;          // 0..31
            float4 v = *(const float4*)&W[(size_t)(kc + r) * DD + q * 4];
            float h0, l0, h1, l1, h2, l2, h3, l3;
            split_tf32(v.x, h0, l0); split_tf32(v.y, h1, l1);
            split_tf32(v.z, h2, l2); split_tf32(v.w, h3, l3);
            float2* p = Wb + r * WS2_STRIDE + q * 4;
            *(float4*)&p[0] = make_float4(h0, l0, h1, l1);
            *(float4*)&p[2] = make_float4(h2, l2, h3, l3);
        }
        __syncthreads();

#pragma unroll
        for (int k8 = 0; k8 < 4; k8++) {
            const int kk = k8 * 8;
            float2 a2[2][4];
#pragma unroll
            for (int mt = 0; mt < 2; mt++) {
                int r = rbase + mt * 16 + gid;
                a2[mt][0] = Xb[r * XS2_STRIDE + kk + tig];
                a2[mt][1] = Xb[(r + 8) * XS2_STRIDE + kk + tig];
                a2[mt][2] = Xb[r * XS2_STRIDE + kk + tig + 4];
                a2[mt][3] = Xb[(r + 8) * XS2_STRIDE + kk + tig + 4];
            }
            uint32_t ah[2][4], al[2][4];
#pragma unroll
            for (int mt = 0; mt < 2; mt++)
#pragma unroll
                for (int j = 0; j < 4; j++) {
                    ah[mt][j] = __float_as_uint(a2[mt][j].x);
                    al[mt][j] = __float_as_uint(a2[mt][j].y);
                }
#pragma unroll
            for (int nt = 0; nt < 8; nt++) {
                int ncol = nbase + nt * 8 + gid;
                float2 b0 = Wb[(kk + tig) * WS2_STRIDE + ncol];
                float2 b1 = Wb[(kk + tig + 4) * WS2_STRIDE + ncol];
                uint32_t bh[2] = {__float_as_uint(b0.x), __float_as_uint(b1.x)};
                uint32_t bl[2] = {__float_as_uint(b0.y), __float_as_uint(b1.y)};
#pragma unroll
                for (int mt = 0; mt < 2; mt++) {
                    MMA_TF32(cd[mt][nt], ah[mt], bh);   // hi*hi
                    MMA_TF32(cd[mt][nt], ah[mt], bl);   // hi*lo
                    MMA_TF32(cd[mt][nt], al[mt], bh);   // lo*hi
                }
            }
        }
    }

    float* dst = (blockIdx.y == 0) ? out : g_s1;
    const bool addb = (blockIdx.y == 0);

#pragma unroll
    for (int nt = 0; nt < 8; nt++) {
        int col = nbase + nt * 8 + tig * 2;
        float b0 = addb ? bias[col] : 0.f;
        float b1 = addb ? bias[col + 1] : 0.f;
#pragma unroll
        for (int mt = 0; mt < 2; mt++) {
            int r0 = row0 + rbase + mt * 16 + gid;
            int r1 = r0 + 8;
            if (r0 < N) {
                float2 t = make_float2(cd[mt][nt][0] + b0, cd[mt][nt][1] + b1);
                *(float2*)&dst[(size_t)r0 * DD + col] = t;
            }
            if (r1 < N) {
                float2 t = make_float2(cd[mt][nt][2] + b0, cd[mt][nt][3] + b1);
                *(float2*)&dst[(size_t)r1 * DD + col] = t;
            }
        }
    }
}

// ---------------------------------------------------------------------------
// Edge aggregation (R8-proven, ~154 us, at L2 roofline): one warp per 32-edge
// batch, coalesced index loads, 4-deep gather->red pipeline, red.add.v4.f32.
// ---------------------------------------------------------------------------
__global__ __launch_bounds__(256) void edge_kernel(
    const int* __restrict__ ei, const float* __restrict__ ev,
    float* __restrict__ out, int E)
{
    const int lane = threadIdx.x & 31;
    int wglob = blockIdx.x * 8 + (threadIdx.x >> 5);
    int e0 = wglob * 32;
    if (e0 >= E) return;

    int e = e0 + lane;
    bool valid = e < E;
    int src = valid ? __ldg(&ei[e]) : 0;
    int dst = valid ? __ldg(&ei[E + e]) : 0;
    float a = valid ? __ldg(&ev[e]) : 0.f;   // a=0 => red adds 0: harmless

    const unsigned FULL = 0xffffffffu;
#pragma unroll 1
    for (int j0 = 0; j0 < 32; j0 += 4) {
        float4 v[4];
        int d[4];
        float s[4];
#pragma unroll
        for (int jj = 0; jj < 4; jj++) {
            int j = j0 + jj;
            int sj = __shfl_sync(FULL, src, j);
            d[jj] = __shfl_sync(FULL, dst, j);
            s[jj] = __shfl_sync(FULL, a, j);
            v[jj] = *(const float4*)(g_s1 + (size_t)sj * DD + lane * 4);
        }
#pragma unroll
        for (int jj = 0; jj < 4; jj++) {
            float4 t = v[jj];
            float sc = s[jj];
            t.x *= sc; t.y *= sc; t.z *= sc; t.w *= sc;
            float* p = out + (size_t)d[jj] * DD + lane * 4;
            asm volatile("red.global.add.v4.f32 [%0], {%1,%2,%3,%4};"
                         :: "l"(p), "f"(t.x), "f"(t.y), "f"(t.z), "f"(t.w)
                         : "memory");
        }
    }
}

extern "C" void kernel_launch(void* const* d_in, const int* in_sizes, int n_in,
                              void* d_out, int out_size)
{
    const float* X    = (const float*)d_in[0];   // [N,128] f32
    const int*   ei   = (const int*)d_in[1];     // [2,E] int32
    const float* ev   = (const float*)d_in[2];   // [E] f32
    const float* W0   = (const float*)d_in[3];   // [128,128] f32
    const float* W1   = (const float*)d_in[4];   // [128,128] f32
    const float* bias = (const float*)d_in[5];   // [128] f32
    float* out = (float*)d_out;

    int N = in_sizes[0] / DD;
    int E = in_sizes[2];

    cudaFuncSetAttribute(gemm_tf32_kernel,
                         cudaFuncAttributeMaxDynamicSharedMemorySize, SMEM_BYTES);

    // k1: 3xTF32 tensor-core dual GEMM, hi/lo packed, single buffer
    int GX = (N + 127) / 128;
    gemm_tf32_kernel<<<dim3(GX, 2), 256, SMEM_BYTES>>>(X, W0, W1, bias, out, N);

    // k2: out[dst] += ev * g_s1[src], warp-batched
    int EB = (E + 32 * 8 - 1) / (32 * 8);        // 6250 blocks
    edge_kernel<<<EB, 256>>>(ei, ev, out, E);
}